// round 10
// baseline (speedup 1.0000x reference)
#include <cuda_runtime.h>

#define S 512
#define H 768
#define NH 12
#define HD 64

// ---------------- scratch (static device memory; no allocation) ----------------
__device__ float g_qp[S * H];            // query proj [s][c]
__device__ float g_kp[S * H];            // key proj
__device__ float g_vp[S * H];            // value proj
__device__ float g_tt[NH * S * H];       // t[h][q][e]
__device__ float g_cb[NH * S];           // cb[h][q]
__device__ float g_score[NH * S * S];    // AC then attn [h][q][k]

// ---------------- f32x2 helpers ----------------
__device__ __forceinline__ unsigned long long pack2(float a, float b) {
    unsigned long long r;
    asm("mov.b64 %0, {%1, %2};" : "=l"(r) : "r"(__float_as_uint(a)), "r"(__float_as_uint(b)));
    return r;
}
__device__ __forceinline__ void unpack2(unsigned long long v, float& a, float& b) {
    unsigned int x, y;
    asm("mov.b64 {%0, %1}, %2;" : "=r"(x), "=r"(y) : "l"(v));
    a = __uint_as_float(x); b = __uint_as_float(y);
}
__device__ __forceinline__ unsigned long long ffma2(unsigned long long a, unsigned long long b,
                                                    unsigned long long c) {
    unsigned long long d;
    asm("fma.rn.f32x2 %0, %1, %2, %3;" : "=l"(d) : "l"(a), "l"(b), "l"(c));
    return d;
}
__device__ __forceinline__ void cp_async16(unsigned int smem_addr, const void* gptr) {
    asm volatile("cp.async.cg.shared.global [%0], [%1], 16;" :: "r"(smem_addr), "l"(gptr));
}
__device__ __forceinline__ void cp_commit() {
    asm volatile("cp.async.commit_group;" ::: "memory");
}
template <int N>
__device__ __forceinline__ void cp_wait() {
    asm volatile("cp.async.wait_group %0;" :: "n"(N) : "memory");
}

// ---------------- 1) proj: C = A @ W^T + b ; 64s x 32c tile, K-tile 64, reg double-buffer ----------------
__global__ void __launch_bounds__(128) proj_kernel(
    const float* __restrict__ q_in, const float* __restrict__ k_in, const float* __restrict__ v_in,
    const float* __restrict__ Wq, const float* __restrict__ bq,
    const float* __restrict__ Wk, const float* __restrict__ bk,
    const float* __restrict__ Wv, const float* __restrict__ bv)
{
    const float* A; const float* W; const float* bias; float* C;
    if (blockIdx.z == 0)      { A = q_in; W = Wq; bias = bq; C = g_qp; }
    else if (blockIdx.z == 1) { A = k_in; W = Wk; bias = bk; C = g_kp; }
    else                      { A = v_in; W = Wv; bias = bv; C = g_vp; }

    const int s0 = blockIdx.x * 64;
    const int c0 = blockIdx.y * 32;
    const int tid = threadIdx.x;

    __shared__ float Ast[64][68];   // [k][s]
    __shared__ float Ws2[64][36];   // [k][c]

    const int sg = tid >> 3;        // 0..15 -> s rows sg*4..+3
    const int cg = tid & 7;         // 0..7  -> c cols cg*4..+3

    unsigned long long acc[4][2];
#pragma unroll
    for (int i = 0; i < 4; i++) { acc[i][0] = 0ULL; acc[i][1] = 0ULL; }

    float4 ra[8], rw[4];
#pragma unroll
    for (int t = 0; t < 8; t++) {
        int f = tid + t * 128;
        ra[t] = *reinterpret_cast<const float4*>(&A[(s0 + (f >> 4)) * H + (f & 15) * 4]);
    }
#pragma unroll
    for (int t = 0; t < 4; t++) {
        int f = tid + t * 128;
        rw[t] = *reinterpret_cast<const float4*>(&W[(c0 + (f >> 4)) * H + (f & 15) * 4]);
    }

    for (int kt = 0; kt < 12; kt++) {
        __syncthreads();
#pragma unroll
        for (int t = 0; t < 8; t++) {
            int f = tid + t * 128;
            int s = f >> 4;
            int k4 = (f & 15) * 4;
            Ast[k4 + 0][s] = ra[t].x; Ast[k4 + 1][s] = ra[t].y;
            Ast[k4 + 2][s] = ra[t].z; Ast[k4 + 3][s] = ra[t].w;
        }
#pragma unroll
        for (int t = 0; t < 4; t++) {
            int f = tid + t * 128;
            int c = f >> 4;
            int k4 = (f & 15) * 4;
            Ws2[k4 + 0][c] = rw[t].x; Ws2[k4 + 1][c] = rw[t].y;
            Ws2[k4 + 2][c] = rw[t].z; Ws2[k4 + 3][c] = rw[t].w;
        }
        __syncthreads();

        if (kt + 1 < 12) {
            const int kb = (kt + 1) * 64;
#pragma unroll
            for (int t = 0; t < 8; t++) {
                int f = tid + t * 128;
                ra[t] = *reinterpret_cast<const float4*>(&A[(s0 + (f >> 4)) * H + kb + (f & 15) * 4]);
            }
#pragma unroll
            for (int t = 0; t < 4; t++) {
                int f = tid + t * 128;
                rw[t] = *reinterpret_cast<const float4*>(&W[(c0 + (f >> 4)) * H + kb + (f & 15) * 4]);
            }
        }

#pragma unroll
        for (int kk = 0; kk < 64; kk++) {
            float4 a4 = *reinterpret_cast<const float4*>(&Ast[kk][sg * 4]);
            ulonglong2 b = *reinterpret_cast<const ulonglong2*>(&Ws2[kk][cg * 4]);
#pragma unroll
            for (int i = 0; i < 4; i++) {
                float av = (&a4.x)[i];
                unsigned long long pp = pack2(av, av);
                acc[i][0] = ffma2(pp, b.x, acc[i][0]);
                acc[i][1] = ffma2(pp, b.y, acc[i][1]);
            }
        }
    }
#pragma unroll
    for (int i = 0; i < 4; i++) {
        int s = s0 + sg * 4 + i;
#pragma unroll
        for (int j = 0; j < 2; j++) {
            float lo, hi; unpack2(acc[i][j], lo, hi);
            int c = c0 + cg * 4 + 2 * j;
            float2 r2; r2.x = lo + bias[c]; r2.y = hi + bias[c + 1];
            *reinterpret_cast<float2*>(&C[s * H + c]) = r2;
        }
    }
}

// ---------------- 2) fused aux kernel: ac (768 blocks) + tt (192) + cbias (48) ----------------
#define AUX_AC_BLOCKS 768
#define AUX_TT_BLOCKS 192
#define AUX_CB_BLOCKS 48
#define AUX_BLOCKS (AUX_AC_BLOCKS + AUX_TT_BLOCKS + AUX_CB_BLOCKS)

__global__ void __launch_bounds__(128) aux_kernel(const float* __restrict__ Wr,
                                                  const float* __restrict__ br,
                                                  const float* __restrict__ u_bias,
                                                  const float* __restrict__ v_bias)
{
    __shared__ float pool[2 * 64 * 68];   // 34.8 KB, carved per branch
    const int b   = blockIdx.x;
    const int tid = threadIdx.x;

    if (b < AUX_AC_BLOCKS) {
        // ---------- AC[h][q][k] = sum_d (qp + u) * kp ; 64q x 64k ----------
        float (*Qst)[68] = reinterpret_cast<float (*)[68]>(pool);
        float (*Ks)[68]  = reinterpret_cast<float (*)[68]>(pool + 64 * 68);

        const int k0 = (b & 7) * 64;
        const int q0 = ((b >> 3) & 7) * 64;
        const int h  = b >> 6;

        const int sg = tid >> 3;
        const int kg = tid & 7;

#pragma unroll
        for (int t = 0; t < 8; t++) {
            int f = tid + t * 128;
            int q = f >> 4;
            int d4 = (f & 15) * 4;
            float4 a = *reinterpret_cast<const float4*>(&g_qp[(q0 + q) * H + h * HD + d4]);
            float4 u = *reinterpret_cast<const float4*>(&u_bias[h * HD + d4]);
            Qst[d4 + 0][q] = a.x + u.x; Qst[d4 + 1][q] = a.y + u.y;
            Qst[d4 + 2][q] = a.z + u.z; Qst[d4 + 3][q] = a.w + u.w;
        }
#pragma unroll
        for (int t = 0; t < 8; t++) {
            int f = tid + t * 128;
            int k = f >> 4;
            int d4 = (f & 15) * 4;
            float4 a = *reinterpret_cast<const float4*>(&g_kp[(k0 + k) * H + h * HD + d4]);
            Ks[d4 + 0][k] = a.x; Ks[d4 + 1][k] = a.y; Ks[d4 + 2][k] = a.z; Ks[d4 + 3][k] = a.w;
        }
        __syncthreads();

        unsigned long long acc[4][4];
#pragma unroll
        for (int i = 0; i < 4; i++)
#pragma unroll
            for (int j = 0; j < 4; j++) acc[i][j] = 0ULL;

#pragma unroll
        for (int d = 0; d < HD; d++) {
            float4 a4 = *reinterpret_cast<const float4*>(&Qst[d][sg * 4]);
            ulonglong2 b0 = *reinterpret_cast<const ulonglong2*>(&Ks[d][kg * 8]);
            ulonglong2 b1 = *reinterpret_cast<const ulonglong2*>(&Ks[d][kg * 8 + 4]);
#pragma unroll
            for (int i = 0; i < 4; i++) {
                float av = (&a4.x)[i];
                unsigned long long pp = pack2(av, av);
                acc[i][0] = ffma2(pp, b0.x, acc[i][0]);
                acc[i][1] = ffma2(pp, b0.y, acc[i][1]);
                acc[i][2] = ffma2(pp, b1.x, acc[i][2]);
                acc[i][3] = ffma2(pp, b1.y, acc[i][3]);
            }
        }
#pragma unroll
        for (int i = 0; i < 4; i++) {
            int q = q0 + sg * 4 + i;
#pragma unroll
            for (int j = 0; j < 4; j++) {
                int k = k0 + kg * 8 + 2 * j;
                *reinterpret_cast<unsigned long long*>(&g_score[(h * S + q) * S + k]) = acc[i][j];
            }
        }
    } else if (b < AUX_AC_BLOCKS + AUX_TT_BLOCKS) {
        // ---------- t[h][q][e] = sum_d (qp + vb) * Wr[h*64+d][e]; 32q x 64e ----------
        float (*Qst)[36] = reinterpret_cast<float (*)[36]>(pool);           // [d][q]
        float (*Ws)[68]  = reinterpret_cast<float (*)[68]>(pool + 64 * 36); // [d][e]

        const int idx = b - AUX_AC_BLOCKS;
        const int e0 = (idx % 12) * 64;
        const int q0 = (idx / 12) * 32;

        const int qg = tid >> 4;
        const int eg = tid & 15;

        for (int h = 0; h < NH; h++) {
#pragma unroll
            for (int t = 0; t < 4; t++) {
                int f = tid + t * 128;
                int q = f >> 4;
                int d4 = (f & 15) * 4;
                float4 a = *reinterpret_cast<const float4*>(&g_qp[(q0 + q) * H + h * HD + d4]);
                float4 vb = *reinterpret_cast<const float4*>(&v_bias[h * HD + d4]);
                Qst[d4 + 0][q] = a.x + vb.x; Qst[d4 + 1][q] = a.y + vb.y;
                Qst[d4 + 2][q] = a.z + vb.z; Qst[d4 + 3][q] = a.w + vb.w;
            }
#pragma unroll
            for (int t = 0; t < 8; t++) {
                int f = tid + t * 128;
                int d = f >> 4;
                int e4 = (f & 15) * 4;
                float4 a = *reinterpret_cast<const float4*>(&Wr[(h * HD + d) * H + e0 + e4]);
                *reinterpret_cast<float4*>(&Ws[d][e4]) = a;
            }
            __syncthreads();

            unsigned long long acc[4][2];
#pragma unroll
            for (int i = 0; i < 4; i++) { acc[i][0] = 0ULL; acc[i][1] = 0ULL; }

#pragma unroll
            for (int d = 0; d < HD; d++) {
                float4 a4 = *reinterpret_cast<const float4*>(&Qst[d][qg * 4]);
                ulonglong2 bb = *reinterpret_cast<const ulonglong2*>(&Ws[d][eg * 4]);
#pragma unroll
                for (int i = 0; i < 4; i++) {
                    float av = (&a4.x)[i];
                    unsigned long long pp = pack2(av, av);
                    acc[i][0] = ffma2(pp, bb.x, acc[i][0]);
                    acc[i][1] = ffma2(pp, bb.y, acc[i][1]);
                }
            }
#pragma unroll
            for (int i = 0; i < 4; i++) {
                int q = q0 + qg * 4 + i;
#pragma unroll
                for (int j = 0; j < 2; j++) {
                    float lo, hi; unpack2(acc[i][j], lo, hi);
                    float2 r2; r2.x = lo; r2.y = hi;
                    *reinterpret_cast<float2*>(&g_tt[(h * S + q) * H + e0 + eg * 4 + 2 * j]) = r2;
                }
            }
            __syncthreads();
        }
    } else {
        // ---------- cb[h][q] = sum_d (qp + vb) * br ----------
        int idx = (b - AUX_AC_BLOCKS - AUX_TT_BLOCKS) * 128 + tid;
        if (idx < NH * S) {
            int h = idx / S, q = idx % S;
            float s = 0.f;
#pragma unroll 8
            for (int d = 0; d < HD; d++)
                s += (g_qp[q * H + h * HD + d] + v_bias[h * HD + d]) * br[h * HD + d];
            g_cb[idx] = s;
        }
    }
}

// ---------------- 3) BD + mask + softmax fused ----------------
// One block per q: 256 threads (8 warps), each warp owns 64 keys (2/thread) with
// its OWN cp.async pipeline: BD_E=16 chunks, 4-buffer ring, prefetch distance 3.
#define BD_E 16                   // e-chunk width
#define BD_PAD 20                 // padded row (floats), 80B (16B-aligned)
#define BD_NCH (H / BD_E)         // 48 chunks
#define BD_TS (H * NH)            // t2s floats: [e][h]
#define BDW_BUF (64 * BD_PAD)     // one per-warp pos buffer (1280 floats = 5120 B)
#define BD_NBUF 4
#define BD_SMEM_BYTES ((BD_TS + 8 * BD_NBUF * BDW_BUF) * 4)   // 36864 + 163840 = 200704 B

__device__ __forceinline__ void bd_issue_warp(const float* src_base, int ch, float* buf, int lane)
{
    unsigned int dbase = (unsigned int)__cvta_generic_to_shared(buf);
    const float* src = src_base + ch * BD_E;
#pragma unroll
    for (int t = 0; t < 8; t++) {
        int seg = lane + t * 32;          // 256 segs: 64 rows x 4 float4
        int row = seg >> 2;
        int c4  = (seg & 3) * 4;
        cp_async16(dbase + (unsigned)(row * BD_PAD + c4) * 4, src + (long)row * H + c4);
    }
}

__global__ void __launch_bounds__(256) bd_kernel(const float* __restrict__ pos,
                                                 const int* __restrict__ key_mask)
{
    extern __shared__ float sm[];
    float* t2s = sm;                        // [e*12 + h]
    __shared__ float red[8][12];
    __shared__ float bmax[12];
    __shared__ float bsum[12];

    const int tid  = threadIdx.x;
    const int wid  = tid >> 5;
    const int lane = tid & 31;
    float* wbufs[BD_NBUF];
#pragma unroll
    for (int i = 0; i < BD_NBUF; i++)
        wbufs[i] = sm + BD_TS + (wid * BD_NBUF + i) * BDW_BUF;

    const int q = blockIdx.x;

    const float* psrc = pos + ((long)q * S + wid * 64) * H;

    // prologue: prefetch chunks 0..2 (warp-local)
    bd_issue_warp(psrc, 0, wbufs[0], lane); cp_commit();
    bd_issue_warp(psrc, 1, wbufs[1], lane); cp_commit();
    bd_issue_warp(psrc, 2, wbufs[2], lane); cp_commit();

    // stage t2s: transpose g_tt[h][q][e] -> t2s[e][h]; 2304 float4 / 256 = 9
#pragma unroll
    for (int t = 0; t < 9; t++) {
        int f = tid + t * 256;
        int h = f / 192;
        int r = f - h * 192;
        int e = r * 4;
        float4 v4 = *reinterpret_cast<const float4*>(&g_tt[(h * S + q) * H + e]);
        t2s[(e + 0) * 12 + h] = v4.x;
        t2s[(e + 1) * 12 + h] = v4.y;
        t2s[(e + 2) * 12 + h] = v4.z;
        t2s[(e + 3) * 12 + h] = v4.w;
    }
    __syncthreads();    // t2s visible; warps free-run from here

    unsigned long long acc0[6], acc1[6];
#pragma unroll
    for (int j = 0; j < 6; j++) { acc0[j] = 0ULL; acc1[j] = 0ULL; }

    const int ra = lane * BD_PAD;
    const int rb = (lane + 32) * BD_PAD;

    for (int ch = 0; ch < BD_NCH; ch++) {
        if (ch + 3 < BD_NCH) {
            bd_issue_warp(psrc, ch + 3, wbufs[(ch + 3) & 3], lane);
            cp_commit();
            cp_wait<3>();          // chunk ch complete; ch+1..ch+3 in flight
        } else if (ch + 2 < BD_NCH) {
            cp_wait<2>();
        } else if (ch + 1 < BD_NCH) {
            cp_wait<1>();
        } else {
            cp_wait<0>();
        }
        __syncwarp();

        const float* bp = wbufs[ch & 3];
        const int e0 = ch * BD_E;
#pragma unroll
        for (int j = 0; j < 4; j++) {
            float4 pa = *reinterpret_cast<const float4*>(&bp[ra + 4 * j]);
            float4 pb = *reinterpret_cast<const float4*>(&bp[rb + 4 * j]);
            const float* tw = &t2s[(e0 + 4 * j) * 12];
#pragma unroll
            for (int i = 0; i < 4; i++) {
                float p0 = (&pa.x)[i];
                float p1 = (&pb.x)[i];
                unsigned long long pp0 = pack2(p0, p0);
                unsigned long long pp1 = pack2(p1, p1);
                const ulonglong2 w0 = *reinterpret_cast<const ulonglong2*>(&tw[i * 12 + 0]);
                const ulonglong2 w1 = *reinterpret_cast<const ulonglong2*>(&tw[i * 12 + 4]);
                const ulonglong2 w2 = *reinterpret_cast<const ulonglong2*>(&tw[i * 12 + 8]);
                acc0[0] = ffma2(pp0, w0.x, acc0[0]);
                acc0[1] = ffma2(pp0, w0.y, acc0[1]);
                acc0[2] = ffma2(pp0, w1.x, acc0[2]);
                acc0[3] = ffma2(pp0, w1.y, acc0[3]);
                acc0[4] = ffma2(pp0, w2.x, acc0[4]);
                acc0[5] = ffma2(pp0, w2.y, acc0[5]);
                acc1[0] = ffma2(pp1, w0.x, acc1[0]);
                acc1[1] = ffma2(pp1, w0.y, acc1[1]);
                acc1[2] = ffma2(pp1, w1.x, acc1[2]);
                acc1[3] = ffma2(pp1, w1.y, acc1[3]);
                acc1[4] = ffma2(pp1, w2.x, acc1[4]);
                acc1[5] = ffma2(pp1, w2.y, acc1[5]);
            }
        }
        __syncwarp();
    }

    // ---- finalize scores: s = (AC + cb + bd) * 0.125, apply mask ----
    const int kA = wid * 64 + lane;
    const int kB = kA + 32;
    const bool mA = (key_mask[kA] == 0);
    const bool mB = (key_mask[kB] == 0);

    float sA[12], sB[12];
#pragma unroll
    for (int j = 0; j < 6; j++) {
        float a0, a1, b0, b1;
        unpack2(acc0[j], a0, a1);
        unpack2(acc1[j], b0, b1);
        int h0 = 2 * j, h1 = 2 * j + 1;
        float c0 = g_cb[h0 * S + q];
        float c1 = g_cb[h1 * S + q];
        int i0 = (h0 * S + q) * S;
        int i1 = (h1 * S + q) * S;
        sA[h0] = (g_score[i0 + kA] + c0 + a0) * 0.125f;
        sA[h1] = (g_score[i1 + kA] + c1 + a1) * 0.125f;
        sB[h0] = (g_score[i0 + kB] + c0 + b0) * 0.125f;
        sB[h1] = (g_score[i1 + kB] + c1 + b1) * 0.125f;
    }
    if (mA) {
#pragma unroll
        for (int h = 0; h < 12; h++) sA[h] = -1e15f;
    }
    if (mB) {
#pragma unroll
        for (int h = 0; h < 12; h++) sB[h] = -1e15f;
    }

    // ---- block max per head ----
    float mh[12];
#pragma unroll
    for (int h = 0; h < 12; h++) mh[h] = fmaxf(sA[h], sB[h]);
#pragma unroll
    for (int o = 16; o > 0; o >>= 1) {
#pragma unroll
        for (int h = 0; h < 12; h++)
            mh[h] = fmaxf(mh[h], __shfl_xor_sync(0xffffffffu, mh[h], o));
    }
    if (lane == 0) {
#pragma unroll
        for (int h = 0; h < 12; h++) red[wid][h] = mh[h];
    }
    __syncthreads();
    if (tid < 12) {
        float m = red[0][tid];
#pragma unroll
        for (int w = 1; w < 8; w++) m = fmaxf(m, red[w][tid]);
        bmax[tid] = m;
    }
    __syncthreads();

    // ---- exp + block sum per head ----
    float eA[12], eB[12], sh[12];
#pragma unroll
    for (int h = 0; h < 12; h++) {
        float m = bmax[h];
        eA[h] = __expf(sA[h] - m);
        eB[h] = __expf(sB[h] - m);
        sh[h] = eA[h] + eB[h];
    }
#pragma unroll
    for (int o = 16; o > 0; o >>= 1) {
#pragma unroll
        for (int h = 0; h < 12; h++)
            sh[h] += __shfl_xor_sync(0xffffffffu, sh[h], o);
    }
    if (lane == 0) {
#pragma unroll
        for (int h = 0; h < 12; h++) red[wid][h] = sh[h];
    }
    __syncthreads();
    if (tid < 12) {
        float s = red[0][tid];
#pragma unroll
        for (int w = 1; w < 8; w++) s += red[w][tid];
        bsum[tid] = 1.0f / s;
    }
    __syncthreads();

    // ---- write attn ----
#pragma unroll
    for (int h = 0; h < 12; h++) {
        float inv = bsum[h];
        int base = (h * S + q) * S;
        g_score[base + kA] = eA[h] * inv;
        g_score[base + kB] = eB[h] * inv;
    }
}

// ---------------- 4) out: 16q x 64d tiles, cp.async double-buffered stages ----------------
#define OUT_ATB (16 * 68)       // At buffer floats
#define OUT_VSB (64 * 68)       // Vs buffer floats

__global__ void __launch_bounds__(128) out_kernel(float* __restrict__ out)
{
    __shared__ float At[2][16][68];   // [buf][q][k]
    __shared__ float Vs[2][64][68];   // [buf][k][d]

    const int q0 = blockIdx.x * 16;
    const int h  = blockIdx.y;
    const int tid = threadIdx.x;

    const int qg = tid >> 4;       // 0..7 -> q rows qg*2, qg*2+1
    const int dg = tid & 15;       // d cols dg*4..+3

    // issue chunk staging (cp.async)
    auto issue = [&](int kc, int buf) {
        unsigned int at_base = (unsigned int)__cvta_generic_to_shared(&At[buf][0][0]);
        unsigned int vs_base = (unsigned int)__cvta_generic_to_shared(&Vs[buf][0][0]);
        // At: 16q x 64k = 256 segs, 2 per thread
#pragma unroll
        for (int t = 0; t < 2; t++) {
            int f = tid + t * 128;
            int qq = f >> 4;
            int k4 = (f & 15) * 4;
            cp_async16(at_base + (unsigned)(qq * 68 + k4) * 4,
                       &g_score[(h * S + q0 + qq) * S + kc * 64 + k4]);
        }
        // Vs: 64k x 64d = 1024 segs, 8 per thread
#pragma unroll
        for (int t = 0; t < 8; t++) {
            int f = tid + t * 128;
            int k = f >> 4;
            int d4 = (f & 15) * 4;
            cp_async16(vs_base + (unsigned)(k * 68 + d4) * 4,
                       &g_vp[(kc * 64 + k) * H + h * HD + d4]);
        }
        cp_commit();
    };

    issue(0, 0);

    unsigned long long acc[2][2];
    acc[0][0] = 0ULL; acc[0][1] = 0ULL; acc[1][0] = 0ULL; acc[1][1] = 0ULL;

    for (int kc = 0; kc < 8; kc++) {
        if (kc + 1 < 8) {
            issue(kc + 1, (kc + 1) & 1);
            cp_wait<1>();
        } else {
            cp_wait<0>();
        }
        __syncthreads();

        const int buf = kc & 1;
#pragma unroll
        for (int kk = 0; kk < 64; kk++) {
            float a0 = At[buf][qg * 2 + 0][kk];
            float a1 = At[buf][qg * 2 + 1][kk];
            ulonglong2 b = *reinterpret_cast<const ulonglong2*>(&Vs[buf][kk][dg * 4]);
            unsigned long long p0 = pack2(a0, a0);
            unsigned long long p1 = pack2(a1, a1);
            acc[0][0] = ffma2(p0, b.x, acc[0][0]);
            acc[0][1] = ffma2(p0, b.y, acc[0][1]);
            acc[1][0] = ffma2(p1, b.x, acc[1][0]);
            acc[1][1] = ffma2(p1, b.y, acc[1][1]);
        }
        __syncthreads();    // buf consumed before it's overwritten two iters later
    }
#pragma unroll
    for (int i = 0; i < 2; i++) {
        int q = q0 + qg * 2 + i;
        float r0, r1, r2, r3;
        unpack2(acc[i][0], r0, r1);
        unpack2(acc[i][1], r2, r3);
        *reinterpret_cast<float4*>(&out[q * H + h * HD + dg * 4]) = make_float4(r0, r1, r2, r3);
    }
}

// ---------------- launch ----------------
extern "C" void kernel_launch(void* const* d_in, const int* in_sizes, int n_in,
                              void* d_out, int out_size)
{
    (void)in_sizes; (void)n_in; (void)out_size;
    const float* key      = (const float*)d_in[0];
    const float* query    = (const float*)d_in[1];
    const float* value    = (const float*)d_in[2];
    const float* pos      = (const float*)d_in[3];
    const int*   key_mask = (const int*)d_in[4];
    const float* Wk = (const float*)d_in[5];
    const float* bk = (const float*)d_in[6];
    const float* Wq = (const float*)d_in[7];
    const float* bq = (const float*)d_in[8];
    const float* Wv = (const float*)d_in[9];
    const float* bv = (const float*)d_in[10];
    const float* Wr = (const float*)d_in[11];
    const float* br = (const float*)d_in[12];
    const float* u_bias = (const float*)d_in[13];
    const float* v_bias = (const float*)d_in[14];
    float* out = (float*)d_out;

    proj_kernel<<<dim3(8, 24, 3), 128>>>(query, key, value, Wq, bq, Wk, bk, Wv, bv);
    aux_kernel<<<AUX_BLOCKS, 128>>>(Wr, br, u_bias, v_bias);

    cudaFuncSetAttribute(bd_kernel, cudaFuncAttributeMaxDynamicSharedMemorySize, BD_SMEM_BYTES);
    bd_kernel<<<S, 256, BD_SMEM_BYTES>>>(pos, key_mask);

    out_kernel<<<dim3(32, NH), 128>>>(out);
}

// round 11
// speedup vs baseline: 1.1235x; 1.1235x over previous
#include <cuda_runtime.h>

#define S 512
#define H 768
#define NH 12
#define HD 64

// ---------------- scratch (static device memory; no allocation) ----------------
__device__ float g_qp[S * H];            // query proj [s][c]
__device__ float g_kp[S * H];            // key proj
__device__ float g_vp[S * H];            // value proj
__device__ float g_tt[NH * S * H];       // t[h][q][e]
__device__ float g_cb[NH * S];           // cb[h][q]
__device__ float g_score[NH * S * S];    // AC then attn [h][q][k]

// ---------------- f32x2 helpers ----------------
__device__ __forceinline__ unsigned long long pack2(float a, float b) {
    unsigned long long r;
    asm("mov.b64 %0, {%1, %2};" : "=l"(r) : "r"(__float_as_uint(a)), "r"(__float_as_uint(b)));
    return r;
}
__device__ __forceinline__ void unpack2(unsigned long long v, float& a, float& b) {
    unsigned int x, y;
    asm("mov.b64 {%0, %1}, %2;" : "=r"(x), "=r"(y) : "l"(v));
    a = __uint_as_float(x); b = __uint_as_float(y);
}
__device__ __forceinline__ unsigned long long ffma2(unsigned long long a, unsigned long long b,
                                                    unsigned long long c) {
    unsigned long long d;
    asm("fma.rn.f32x2 %0, %1, %2, %3;" : "=l"(d) : "l"(a), "l"(b), "l"(c));
    return d;
}
__device__ __forceinline__ void cp_async16(unsigned int smem_addr, const void* gptr) {
    asm volatile("cp.async.cg.shared.global [%0], [%1], 16;" :: "r"(smem_addr), "l"(gptr));
}
__device__ __forceinline__ void cp_commit() {
    asm volatile("cp.async.commit_group;" ::: "memory");
}
template <int N>
__device__ __forceinline__ void cp_wait() {
    asm volatile("cp.async.wait_group %0;" :: "n"(N) : "memory");
}

// ---------------- 1) proj: C = A @ W^T + b ; 64s x 32c tile, K-tile 64, reg double-buffer ----------------
__global__ void __launch_bounds__(128) proj_kernel(
    const float* __restrict__ q_in, const float* __restrict__ k_in, const float* __restrict__ v_in,
    const float* __restrict__ Wq, const float* __restrict__ bq,
    const float* __restrict__ Wk, const float* __restrict__ bk,
    const float* __restrict__ Wv, const float* __restrict__ bv)
{
    const float* A; const float* W; const float* bias; float* C;
    if (blockIdx.z == 0)      { A = q_in; W = Wq; bias = bq; C = g_qp; }
    else if (blockIdx.z == 1) { A = k_in; W = Wk; bias = bk; C = g_kp; }
    else                      { A = v_in; W = Wv; bias = bv; C = g_vp; }

    const int s0 = blockIdx.x * 64;
    const int c0 = blockIdx.y * 32;
    const int tid = threadIdx.x;

    __shared__ float Ast[64][68];   // [k][s]
    __shared__ float Ws2[64][36];   // [k][c]

    const int sg = tid >> 3;        // 0..15 -> s rows sg*4..+3
    const int cg = tid & 7;         // 0..7  -> c cols cg*4..+3

    unsigned long long acc[4][2];
#pragma unroll
    for (int i = 0; i < 4; i++) { acc[i][0] = 0ULL; acc[i][1] = 0ULL; }

    float4 ra[8], rw[4];
#pragma unroll
    for (int t = 0; t < 8; t++) {
        int f = tid + t * 128;
        ra[t] = *reinterpret_cast<const float4*>(&A[(s0 + (f >> 4)) * H + (f & 15) * 4]);
    }
#pragma unroll
    for (int t = 0; t < 4; t++) {
        int f = tid + t * 128;
        rw[t] = *reinterpret_cast<const float4*>(&W[(c0 + (f >> 4)) * H + (f & 15) * 4]);
    }

    for (int kt = 0; kt < 12; kt++) {
        __syncthreads();
#pragma unroll
        for (int t = 0; t < 8; t++) {
            int f = tid + t * 128;
            int s = f >> 4;
            int k4 = (f & 15) * 4;
            Ast[k4 + 0][s] = ra[t].x; Ast[k4 + 1][s] = ra[t].y;
            Ast[k4 + 2][s] = ra[t].z; Ast[k4 + 3][s] = ra[t].w;
        }
#pragma unroll
        for (int t = 0; t < 4; t++) {
            int f = tid + t * 128;
            int c = f >> 4;
            int k4 = (f & 15) * 4;
            Ws2[k4 + 0][c] = rw[t].x; Ws2[k4 + 1][c] = rw[t].y;
            Ws2[k4 + 2][c] = rw[t].z; Ws2[k4 + 3][c] = rw[t].w;
        }
        __syncthreads();

        if (kt + 1 < 12) {
            const int kb = (kt + 1) * 64;
#pragma unroll
            for (int t = 0; t < 8; t++) {
                int f = tid + t * 128;
                ra[t] = *reinterpret_cast<const float4*>(&A[(s0 + (f >> 4)) * H + kb + (f & 15) * 4]);
            }
#pragma unroll
            for (int t = 0; t < 4; t++) {
                int f = tid + t * 128;
                rw[t] = *reinterpret_cast<const float4*>(&W[(c0 + (f >> 4)) * H + kb + (f & 15) * 4]);
            }
        }

#pragma unroll
        for (int kk = 0; kk < 64; kk++) {
            float4 a4 = *reinterpret_cast<const float4*>(&Ast[kk][sg * 4]);
            ulonglong2 b = *reinterpret_cast<const ulonglong2*>(&Ws2[kk][cg * 4]);
#pragma unroll
            for (int i = 0; i < 4; i++) {
                float av = (&a4.x)[i];
                unsigned long long pp = pack2(av, av);
                acc[i][0] = ffma2(pp, b.x, acc[i][0]);
                acc[i][1] = ffma2(pp, b.y, acc[i][1]);
            }
        }
    }
#pragma unroll
    for (int i = 0; i < 4; i++) {
        int s = s0 + sg * 4 + i;
#pragma unroll
        for (int j = 0; j < 2; j++) {
            float lo, hi; unpack2(acc[i][j], lo, hi);
            int c = c0 + cg * 4 + 2 * j;
            float2 r2; r2.x = lo + bias[c]; r2.y = hi + bias[c + 1];
            *reinterpret_cast<float2*>(&C[s * H + c]) = r2;
        }
    }
}

// ---------------- 2) fused aux kernel: ac (768 blocks) + tt (192) + cbias (48) ----------------
#define AUX_AC_BLOCKS 768
#define AUX_TT_BLOCKS 192
#define AUX_CB_BLOCKS 48
#define AUX_BLOCKS (AUX_AC_BLOCKS + AUX_TT_BLOCKS + AUX_CB_BLOCKS)

__global__ void __launch_bounds__(128) aux_kernel(const float* __restrict__ Wr,
                                                  const float* __restrict__ br,
                                                  const float* __restrict__ u_bias,
                                                  const float* __restrict__ v_bias)
{
    __shared__ float pool[2 * 64 * 68];   // 34.8 KB, carved per branch
    const int b   = blockIdx.x;
    const int tid = threadIdx.x;

    if (b < AUX_AC_BLOCKS) {
        // ---------- AC[h][q][k] = sum_d (qp + u) * kp ; 64q x 64k ----------
        float (*Qst)[68] = reinterpret_cast<float (*)[68]>(pool);
        float (*Ks)[68]  = reinterpret_cast<float (*)[68]>(pool + 64 * 68);

        const int k0 = (b & 7) * 64;
        const int q0 = ((b >> 3) & 7) * 64;
        const int h  = b >> 6;

        const int sg = tid >> 3;
        const int kg = tid & 7;

#pragma unroll
        for (int t = 0; t < 8; t++) {
            int f = tid + t * 128;
            int q = f >> 4;
            int d4 = (f & 15) * 4;
            float4 a = *reinterpret_cast<const float4*>(&g_qp[(q0 + q) * H + h * HD + d4]);
            float4 u = *reinterpret_cast<const float4*>(&u_bias[h * HD + d4]);
            Qst[d4 + 0][q] = a.x + u.x; Qst[d4 + 1][q] = a.y + u.y;
            Qst[d4 + 2][q] = a.z + u.z; Qst[d4 + 3][q] = a.w + u.w;
        }
#pragma unroll
        for (int t = 0; t < 8; t++) {
            int f = tid + t * 128;
            int k = f >> 4;
            int d4 = (f & 15) * 4;
            float4 a = *reinterpret_cast<const float4*>(&g_kp[(k0 + k) * H + h * HD + d4]);
            Ks[d4 + 0][k] = a.x; Ks[d4 + 1][k] = a.y; Ks[d4 + 2][k] = a.z; Ks[d4 + 3][k] = a.w;
        }
        __syncthreads();

        unsigned long long acc[4][4];
#pragma unroll
        for (int i = 0; i < 4; i++)
#pragma unroll
            for (int j = 0; j < 4; j++) acc[i][j] = 0ULL;

#pragma unroll
        for (int d = 0; d < HD; d++) {
            float4 a4 = *reinterpret_cast<const float4*>(&Qst[d][sg * 4]);
            ulonglong2 b0 = *reinterpret_cast<const ulonglong2*>(&Ks[d][kg * 8]);
            ulonglong2 b1 = *reinterpret_cast<const ulonglong2*>(&Ks[d][kg * 8 + 4]);
#pragma unroll
            for (int i = 0; i < 4; i++) {
                float av = (&a4.x)[i];
                unsigned long long pp = pack2(av, av);
                acc[i][0] = ffma2(pp, b0.x, acc[i][0]);
                acc[i][1] = ffma2(pp, b0.y, acc[i][1]);
                acc[i][2] = ffma2(pp, b1.x, acc[i][2]);
                acc[i][3] = ffma2(pp, b1.y, acc[i][3]);
            }
        }
#pragma unroll
        for (int i = 0; i < 4; i++) {
            int q = q0 + sg * 4 + i;
#pragma unroll
            for (int j = 0; j < 4; j++) {
                int k = k0 + kg * 8 + 2 * j;
                *reinterpret_cast<unsigned long long*>(&g_score[(h * S + q) * S + k]) = acc[i][j];
            }
        }
    } else if (b < AUX_AC_BLOCKS + AUX_TT_BLOCKS) {
        // ---------- t[h][q][e] = sum_d (qp + vb) * Wr[h*64+d][e]; 32q x 64e ----------
        float (*Qst)[36] = reinterpret_cast<float (*)[36]>(pool);           // [d][q]
        float (*Ws)[68]  = reinterpret_cast<float (*)[68]>(pool + 64 * 36); // [d][e]

        const int idx = b - AUX_AC_BLOCKS;
        const int e0 = (idx % 12) * 64;
        const int q0 = (idx / 12) * 32;

        const int qg = tid >> 4;
        const int eg = tid & 15;

        for (int h = 0; h < NH; h++) {
#pragma unroll
            for (int t = 0; t < 4; t++) {
                int f = tid + t * 128;
                int q = f >> 4;
                int d4 = (f & 15) * 4;
                float4 a = *reinterpret_cast<const float4*>(&g_qp[(q0 + q) * H + h * HD + d4]);
                float4 vb = *reinterpret_cast<const float4*>(&v_bias[h * HD + d4]);
                Qst[d4 + 0][q] = a.x + vb.x; Qst[d4 + 1][q] = a.y + vb.y;
                Qst[d4 + 2][q] = a.z + vb.z; Qst[d4 + 3][q] = a.w + vb.w;
            }
#pragma unroll
            for (int t = 0; t < 8; t++) {
                int f = tid + t * 128;
                int d = f >> 4;
                int e4 = (f & 15) * 4;
                float4 a = *reinterpret_cast<const float4*>(&Wr[(h * HD + d) * H + e0 + e4]);
                *reinterpret_cast<float4*>(&Ws[d][e4]) = a;
            }
            __syncthreads();

            unsigned long long acc[4][2];
#pragma unroll
            for (int i = 0; i < 4; i++) { acc[i][0] = 0ULL; acc[i][1] = 0ULL; }

#pragma unroll
            for (int d = 0; d < HD; d++) {
                float4 a4 = *reinterpret_cast<const float4*>(&Qst[d][qg * 4]);
                ulonglong2 bb = *reinterpret_cast<const ulonglong2*>(&Ws[d][eg * 4]);
#pragma unroll
                for (int i = 0; i < 4; i++) {
                    float av = (&a4.x)[i];
                    unsigned long long pp = pack2(av, av);
                    acc[i][0] = ffma2(pp, bb.x, acc[i][0]);
                    acc[i][1] = ffma2(pp, bb.y, acc[i][1]);
                }
            }
#pragma unroll
            for (int i = 0; i < 4; i++) {
                int q = q0 + qg * 4 + i;
#pragma unroll
                for (int j = 0; j < 2; j++) {
                    float lo, hi; unpack2(acc[i][j], lo, hi);
                    float2 r2; r2.x = lo; r2.y = hi;
                    *reinterpret_cast<float2*>(&g_tt[(h * S + q) * H + e0 + eg * 4 + 2 * j]) = r2;
                }
            }
            __syncthreads();
        }
    } else {
        // ---------- cb[h][q] = sum_d (qp + vb) * br ----------
        int idx = (b - AUX_AC_BLOCKS - AUX_TT_BLOCKS) * 128 + tid;
        if (idx < NH * S) {
            int h = idx / S, q = idx % S;
            float s = 0.f;
#pragma unroll 8
            for (int d = 0; d < HD; d++)
                s += (g_qp[q * H + h * HD + d] + v_bias[h * HD + d]) * br[h * HD + d];
            g_cb[idx] = s;
        }
    }
}

// ---------------- 3) BD + mask + softmax fused (R7/R9 proven config) ----------------
// One block per q: 256 threads (8 warps), each warp owns 64 keys (2/thread) with
// its OWN double-buffered cp.async pipeline (BD_E=32, distance 1).
#define BD_E 32                   // e-chunk width
#define BD_PAD 36                 // padded row (floats)
#define BD_NCH (H / BD_E)         // 24 chunks
#define BD_TS (H * NH)            // t2s floats: [e][h]
#define BDW_BUF (64 * BD_PAD)     // one per-warp pos buffer (2304 floats = 9216 B)
#define BD_SMEM_BYTES ((BD_TS + 8 * 2 * BDW_BUF) * 4)   // 184320 B

__device__ __forceinline__ void bd_issue_warp(const float* src_base, int ch, float* buf, int lane)
{
    unsigned int dbase = (unsigned int)__cvta_generic_to_shared(buf);
    const float* src = src_base + ch * BD_E;
#pragma unroll
    for (int t = 0; t < 16; t++) {
        int seg = lane + t * 32;          // 512 segs: 64 rows x 8 float4
        int row = seg >> 3;
        int c4  = (seg & 7) * 4;
        cp_async16(dbase + (unsigned)(row * BD_PAD + c4) * 4, src + (long)row * H + c4);
    }
}

__global__ void __launch_bounds__(256) bd_kernel(const float* __restrict__ pos,
                                                 const int* __restrict__ key_mask)
{
    extern __shared__ float sm[];
    float* t2s = sm;                        // [e*12 + h]
    __shared__ float red[8][12];
    __shared__ float bmax[12];
    __shared__ float bsum[12];

    const int tid  = threadIdx.x;
    const int wid  = tid >> 5;
    const int lane = tid & 31;
    float* wbuf0 = sm + BD_TS + wid * 2 * BDW_BUF;
    float* wbuf1 = wbuf0 + BDW_BUF;

    const int q = blockIdx.x;

    const float* psrc = pos + ((long)q * S + wid * 64) * H;

    bd_issue_warp(psrc, 0, wbuf0, lane);
    cp_commit();

#pragma unroll
    for (int t = 0; t < 9; t++) {
        int f = tid + t * 256;
        int h = f / 192;
        int r = f - h * 192;
        int e = r * 4;
        float4 v4 = *reinterpret_cast<const float4*>(&g_tt[(h * S + q) * H + e]);
        t2s[(e + 0) * 12 + h] = v4.x;
        t2s[(e + 1) * 12 + h] = v4.y;
        t2s[(e + 2) * 12 + h] = v4.z;
        t2s[(e + 3) * 12 + h] = v4.w;
    }
    __syncthreads();    // t2s visible; warps free-run from here

    unsigned long long acc0[6], acc1[6];
#pragma unroll
    for (int j = 0; j < 6; j++) { acc0[j] = 0ULL; acc1[j] = 0ULL; }

    const int ra36 = lane * BD_PAD;
    const int rb36 = (lane + 32) * BD_PAD;

    for (int ch = 0; ch < BD_NCH; ch++) {
        if (ch + 1 < BD_NCH) {
            bd_issue_warp(psrc, ch + 1, ((ch + 1) & 1) ? wbuf1 : wbuf0, lane);
            cp_commit();
            cp_wait<1>();
        } else {
            cp_wait<0>();
        }
        __syncwarp();

        const float* bp = (ch & 1) ? wbuf1 : wbuf0;
        const int e0 = ch * BD_E;
#pragma unroll
        for (int j = 0; j < 8; j++) {
            float4 pa = *reinterpret_cast<const float4*>(&bp[ra36 + 4 * j]);
            float4 pb = *reinterpret_cast<const float4*>(&bp[rb36 + 4 * j]);
            const float* tw = &t2s[(e0 + 4 * j) * 12];
#pragma unroll
            for (int i = 0; i < 4; i++) {
                float p0 = (&pa.x)[i];
                float p1 = (&pb.x)[i];
                unsigned long long pp0 = pack2(p0, p0);
                unsigned long long pp1 = pack2(p1, p1);
                const ulonglong2 w0 = *reinterpret_cast<const ulonglong2*>(&tw[i * 12 + 0]);
                const ulonglong2 w1 = *reinterpret_cast<const ulonglong2*>(&tw[i * 12 + 4]);
                const ulonglong2 w2 = *reinterpret_cast<const ulonglong2*>(&tw[i * 12 + 8]);
                acc0[0] = ffma2(pp0, w0.x, acc0[0]);
                acc0[1] = ffma2(pp0, w0.y, acc0[1]);
                acc0[2] = ffma2(pp0, w1.x, acc0[2]);
                acc0[3] = ffma2(pp0, w1.y, acc0[3]);
                acc0[4] = ffma2(pp0, w2.x, acc0[4]);
                acc0[5] = ffma2(pp0, w2.y, acc0[5]);
                acc1[0] = ffma2(pp1, w0.x, acc1[0]);
                acc1[1] = ffma2(pp1, w0.y, acc1[1]);
                acc1[2] = ffma2(pp1, w1.x, acc1[2]);
                acc1[3] = ffma2(pp1, w1.y, acc1[3]);
                acc1[4] = ffma2(pp1, w2.x, acc1[4]);
                acc1[5] = ffma2(pp1, w2.y, acc1[5]);
            }
        }
        __syncwarp();
    }

    // ---- finalize scores: s = (AC + cb + bd) * 0.125, apply mask ----
    const int kA = wid * 64 + lane;
    const int kB = kA + 32;
    const bool mA = (key_mask[kA] == 0);
    const bool mB = (key_mask[kB] == 0);

    float sA[12], sB[12];
#pragma unroll
    for (int j = 0; j < 6; j++) {
        float a0, a1, b0, b1;
        unpack2(acc0[j], a0, a1);
        unpack2(acc1[j], b0, b1);
        int h0 = 2 * j, h1 = 2 * j + 1;
        float c0 = g_cb[h0 * S + q];
        float c1 = g_cb[h1 * S + q];
        int i0 = (h0 * S + q) * S;
        int i1 = (h1 * S + q) * S;
        sA[h0] = (g_score[i0 + kA] + c0 + a0) * 0.125f;
        sA[h1] = (g_score[i1 + kA] + c1 + a1) * 0.125f;
        sB[h0] = (g_score[i0 + kB] + c0 + b0) * 0.125f;
        sB[h1] = (g_score[i1 + kB] + c1 + b1) * 0.125f;
    }
    if (mA) {
#pragma unroll
        for (int h = 0; h < 12; h++) sA[h] = -1e15f;
    }
    if (mB) {
#pragma unroll
        for (int h = 0; h < 12; h++) sB[h] = -1e15f;
    }

    // ---- block max per head ----
    float mh[12];
#pragma unroll
    for (int h = 0; h < 12; h++) mh[h] = fmaxf(sA[h], sB[h]);
#pragma unroll
    for (int o = 16; o > 0; o >>= 1) {
#pragma unroll
        for (int h = 0; h < 12; h++)
            mh[h] = fmaxf(mh[h], __shfl_xor_sync(0xffffffffu, mh[h], o));
    }
    if (lane == 0) {
#pragma unroll
        for (int h = 0; h < 12; h++) red[wid][h] = mh[h];
    }
    __syncthreads();
    if (tid < 12) {
        float m = red[0][tid];
#pragma unroll
        for (int w = 1; w < 8; w++) m = fmaxf(m, red[w][tid]);
        bmax[tid] = m;
    }
    __syncthreads();

    // ---- exp + block sum per head ----
    float eA[12], eB[12], sh[12];
#pragma unroll
    for (int h = 0; h < 12; h++) {
        float m = bmax[h];
        eA[h] = __expf(sA[h] - m);
        eB[h] = __expf(sB[h] - m);
        sh[h] = eA[h] + eB[h];
    }
#pragma unroll
    for (int o = 16; o > 0; o >>= 1) {
#pragma unroll
        for (int h = 0; h < 12; h++)
            sh[h] += __shfl_xor_sync(0xffffffffu, sh[h], o);
    }
    if (lane == 0) {
#pragma unroll
        for (int h = 0; h < 12; h++) red[wid][h] = sh[h];
    }
    __syncthreads();
    if (tid < 12) {
        float s = red[0][tid];
#pragma unroll
        for (int w = 1; w < 8; w++) s += red[w][tid];
        bsum[tid] = 1.0f / s;
    }
    __syncthreads();

    // ---- write attn ----
#pragma unroll
    for (int h = 0; h < 12; h++) {
        float inv = bsum[h];
        int base = (h * S + q) * S;
        g_score[base + kA] = eA[h] * inv;
        g_score[base + kB] = eB[h] * inv;
    }
}

// ---------------- 4) out: 16q x 64d tiles, cp.async double-buffered stages (R10 proven) ----------------
__global__ void __launch_bounds__(128) out_kernel(float* __restrict__ out)
{
    __shared__ float At[2][16][68];   // [buf][q][k]
    __shared__ float Vs[2][64][68];   // [buf][k][d]

    const int q0 = blockIdx.x * 16;
    const int h  = blockIdx.y;
    const int tid = threadIdx.x;

    const int qg = tid >> 4;       // 0..7 -> q rows qg*2, qg*2+1
    const int dg = tid & 15;       // d cols dg*4..+3

    auto issue = [&](int kc, int buf) {
        unsigned int at_base = (unsigned int)__cvta_generic_to_shared(&At[buf][0][0]);
        unsigned int vs_base = (unsigned int)__cvta_generic_to_shared(&Vs[buf][0][0]);
#pragma unroll
        for (int t = 0; t < 2; t++) {
            int f = tid + t * 128;
            int qq = f >> 4;
            int k4 = (f & 15) * 4;
            cp_async16(at_base + (unsigned)(qq * 68 + k4) * 4,
                       &g_score[(h * S + q0 + qq) * S + kc * 64 + k4]);
        }
#pragma unroll
        for (int t = 0; t < 8; t++) {
            int f = tid + t * 128;
            int k = f >> 4;
            int d4 = (f & 15) * 4;
            cp_async16(vs_base + (unsigned)(k * 68 + d4) * 4,
                       &g_vp[(kc * 64 + k) * H + h * HD + d4]);
        }
        cp_commit();
    };

    issue(0, 0);

    unsigned long long acc[2][2];
    acc[0][0] = 0ULL; acc[0][1] = 0ULL; acc[1][0] = 0ULL; acc[1][1] = 0ULL;

    for (int kc = 0; kc < 8; kc++) {
        if (kc + 1 < 8) {
            issue(kc + 1, (kc + 1) & 1);
            cp_wait<1>();
        } else {
            cp_wait<0>();
        }
        __syncthreads();

        const int buf = kc & 1;
#pragma unroll
        for (int kk = 0; kk < 64; kk++) {
            float a0 = At[buf][qg * 2 + 0][kk];
            float a1 = At[buf][qg * 2 + 1][kk];
            ulonglong2 b = *reinterpret_cast<const ulonglong2*>(&Vs[buf][kk][dg * 4]);
            unsigned long long p0 = pack2(a0, a0);
            unsigned long long p1 = pack2(a1, a1);
            acc[0][0] = ffma2(p0, b.x, acc[0][0]);
            acc[0][1] = ffma2(p0, b.y, acc[0][1]);
            acc[1][0] = ffma2(p1, b.x, acc[1][0]);
            acc[1][1] = ffma2(p1, b.y, acc[1][1]);
        }
        __syncthreads();
    }
#pragma unroll
    for (int i = 0; i < 2; i++) {
        int q = q0 + qg * 2 + i;
        float r0, r1, r2, r3;
        unpack2(acc[i][0], r0, r1);
        unpack2(acc[i][1], r2, r3);
        *reinterpret_cast<float4*>(&out[q * H + h * HD + dg * 4]) = make_float4(r0, r1, r2, r3);
    }
}

// ---------------- launch ----------------
extern "C" void kernel_launch(void* const* d_in, const int* in_sizes, int n_in,
                              void* d_out, int out_size)
{
    (void)in_sizes; (void)n_in; (void)out_size;
    const float* key      = (const float*)d_in[0];
    const float* query    = (const float*)d_in[1];
    const float* value    = (const float*)d_in[2];
    const float* pos      = (const float*)d_in[3];
    const int*   key_mask = (const int*)d_in[4];
    const float* Wk = (const float*)d_in[5];
    const float* bk = (const float*)d_in[6];
    const float* Wq = (const float*)d_in[7];
    const float* bq = (const float*)d_in[8];
    const float* Wv = (const float*)d_in[9];
    const float* bv = (const float*)d_in[10];
    const float* Wr = (const float*)d_in[11];
    const float* br = (const float*)d_in[12];
    const float* u_bias = (const float*)d_in[13];
    const float* v_bias = (const float*)d_in[14];
    float* out = (float*)d_out;

    proj_kernel<<<dim3(8, 24, 3), 128>>>(query, key, value, Wq, bq, Wk, bk, Wv, bv);
    aux_kernel<<<AUX_BLOCKS, 128>>>(Wr, br, u_bias, v_bias);

    cudaFuncSetAttribute(bd_kernel, cudaFuncAttributeMaxDynamicSharedMemorySize, BD_SMEM_BYTES);
    bd_kernel<<<S, 256, BD_SMEM_BYTES>>>(pos, key_mask);

    out_kernel<<<dim3(32, NH), 128>>>(out);
}

// round 12
// speedup vs baseline: 1.1318x; 1.0074x over previous
#include <cuda_runtime.h>

#define S 512
#define H 768
#define NH 12
#define HD 64

// ---------------- scratch (static device memory; no allocation) ----------------
__device__ float g_qp[S * H];            // query proj [s][c]
__device__ float g_kp[S * H];            // key proj
__device__ float g_vp[S * H];            // value proj
__device__ float g_tt[NH * S * H];       // t[h][q][e]
__device__ float g_cb[NH * S];           // cb[h][q]
__device__ float g_score[NH * S * S];    // AC then attn [h][q][k]

// ---------------- f32x2 helpers ----------------
__device__ __forceinline__ unsigned long long pack2(float a, float b) {
    unsigned long long r;
    asm("mov.b64 %0, {%1, %2};" : "=l"(r) : "r"(__float_as_uint(a)), "r"(__float_as_uint(b)));
    return r;
}
__device__ __forceinline__ void unpack2(unsigned long long v, float& a, float& b) {
    unsigned int x, y;
    asm("mov.b64 {%0, %1}, %2;" : "=r"(x), "=r"(y) : "l"(v));
    a = __uint_as_float(x); b = __uint_as_float(y);
}
__device__ __forceinline__ unsigned long long ffma2(unsigned long long a, unsigned long long b,
                                                    unsigned long long c) {
    unsigned long long d;
    asm("fma.rn.f32x2 %0, %1, %2, %3;" : "=l"(d) : "l"(a), "l"(b), "l"(c));
    return d;
}
__device__ __forceinline__ void cp_async16(unsigned int smem_addr, const void* gptr) {
    asm volatile("cp.async.cg.shared.global [%0], [%1], 16;" :: "r"(smem_addr), "l"(gptr));
}
__device__ __forceinline__ void cp_commit() {
    asm volatile("cp.async.commit_group;" ::: "memory");
}
template <int N>
__device__ __forceinline__ void cp_wait() {
    asm volatile("cp.async.wait_group %0;" :: "n"(N) : "memory");
}

// ---------------- 1) proj: C = A @ W^T + b ; 64s x 32c tile, K-tile 64, reg double-buffer ----------------
__global__ void __launch_bounds__(128) proj_kernel(
    const float* __restrict__ q_in, const float* __restrict__ k_in, const float* __restrict__ v_in,
    const float* __restrict__ Wq, const float* __restrict__ bq,
    const float* __restrict__ Wk, const float* __restrict__ bk,
    const float* __restrict__ Wv, const float* __restrict__ bv)
{
    const float* A; const float* W; const float* bias; float* C;
    if (blockIdx.z == 0)      { A = q_in; W = Wq; bias = bq; C = g_qp; }
    else if (blockIdx.z == 1) { A = k_in; W = Wk; bias = bk; C = g_kp; }
    else                      { A = v_in; W = Wv; bias = bv; C = g_vp; }

    const int s0 = blockIdx.x * 64;
    const int c0 = blockIdx.y * 32;
    const int tid = threadIdx.x;

    __shared__ float Ast[64][68];   // [k][s]
    __shared__ float Ws2[64][36];   // [k][c]

    const int sg = tid >> 3;        // 0..15 -> s rows sg*4..+3
    const int cg = tid & 7;         // 0..7  -> c cols cg*4..+3

    unsigned long long acc[4][2];
#pragma unroll
    for (int i = 0; i < 4; i++) { acc[i][0] = 0ULL; acc[i][1] = 0ULL; }

    float4 ra[8], rw[4];
#pragma unroll
    for (int t = 0; t < 8; t++) {
        int f = tid + t * 128;
        ra[t] = *reinterpret_cast<const float4*>(&A[(s0 + (f >> 4)) * H + (f & 15) * 4]);
    }
#pragma unroll
    for (int t = 0; t < 4; t++) {
        int f = tid + t * 128;
        rw[t] = *reinterpret_cast<const float4*>(&W[(c0 + (f >> 4)) * H + (f & 15) * 4]);
    }

    for (int kt = 0; kt < 12; kt++) {
        __syncthreads();
#pragma unroll
        for (int t = 0; t < 8; t++) {
            int f = tid + t * 128;
            int s = f >> 4;
            int k4 = (f & 15) * 4;
            Ast[k4 + 0][s] = ra[t].x; Ast[k4 + 1][s] = ra[t].y;
            Ast[k4 + 2][s] = ra[t].z; Ast[k4 + 3][s] = ra[t].w;
        }
#pragma unroll
        for (int t = 0; t < 4; t++) {
            int f = tid + t * 128;
            int c = f >> 4;
            int k4 = (f & 15) * 4;
            Ws2[k4 + 0][c] = rw[t].x; Ws2[k4 + 1][c] = rw[t].y;
            Ws2[k4 + 2][c] = rw[t].z; Ws2[k4 + 3][c] = rw[t].w;
        }
        __syncthreads();

        if (kt + 1 < 12) {
            const int kb = (kt + 1) * 64;
#pragma unroll
            for (int t = 0; t < 8; t++) {
                int f = tid + t * 128;
                ra[t] = *reinterpret_cast<const float4*>(&A[(s0 + (f >> 4)) * H + kb + (f & 15) * 4]);
            }
#pragma unroll
            for (int t = 0; t < 4; t++) {
                int f = tid + t * 128;
                rw[t] = *reinterpret_cast<const float4*>(&W[(c0 + (f >> 4)) * H + kb + (f & 15) * 4]);
            }
        }

#pragma unroll
        for (int kk = 0; kk < 64; kk++) {
            float4 a4 = *reinterpret_cast<const float4*>(&Ast[kk][sg * 4]);
            ulonglong2 b = *reinterpret_cast<const ulonglong2*>(&Ws2[kk][cg * 4]);
#pragma unroll
            for (int i = 0; i < 4; i++) {
                float av = (&a4.x)[i];
                unsigned long long pp = pack2(av, av);
                acc[i][0] = ffma2(pp, b.x, acc[i][0]);
                acc[i][1] = ffma2(pp, b.y, acc[i][1]);
            }
        }
    }
#pragma unroll
    for (int i = 0; i < 4; i++) {
        int s = s0 + sg * 4 + i;
#pragma unroll
        for (int j = 0; j < 2; j++) {
            float lo, hi; unpack2(acc[i][j], lo, hi);
            int c = c0 + cg * 4 + 2 * j;
            float2 r2; r2.x = lo + bias[c]; r2.y = hi + bias[c + 1];
            *reinterpret_cast<float2*>(&C[s * H + c]) = r2;
        }
    }
}

// ---------------- 2) fused aux kernel: ac (768 blocks) + tt (192) + cbias (48) ----------------
#define AUX_AC_BLOCKS 768
#define AUX_TT_BLOCKS 192
#define AUX_CB_BLOCKS 48
#define AUX_BLOCKS (AUX_AC_BLOCKS + AUX_TT_BLOCKS + AUX_CB_BLOCKS)

__global__ void __launch_bounds__(128) aux_kernel(const float* __restrict__ Wr,
                                                  const float* __restrict__ br,
                                                  const float* __restrict__ u_bias,
                                                  const float* __restrict__ v_bias)
{
    __shared__ float pool[2 * 64 * 68];   // 34.8 KB, carved per branch
    const int b   = blockIdx.x;
    const int tid = threadIdx.x;

    if (b < AUX_AC_BLOCKS) {
        // ---------- AC[h][q][k] = sum_d (qp + u) * kp ; 64q x 64k ----------
        float (*Qst)[68] = reinterpret_cast<float (*)[68]>(pool);
        float (*Ks)[68]  = reinterpret_cast<float (*)[68]>(pool + 64 * 68);

        const int k0 = (b & 7) * 64;
        const int q0 = ((b >> 3) & 7) * 64;
        const int h  = b >> 6;

        const int sg = tid >> 3;
        const int kg = tid & 7;

#pragma unroll
        for (int t = 0; t < 8; t++) {
            int f = tid + t * 128;
            int q = f >> 4;
            int d4 = (f & 15) * 4;
            float4 a = *reinterpret_cast<const float4*>(&g_qp[(q0 + q) * H + h * HD + d4]);
            float4 u = *reinterpret_cast<const float4*>(&u_bias[h * HD + d4]);
            Qst[d4 + 0][q] = a.x + u.x; Qst[d4 + 1][q] = a.y + u.y;
            Qst[d4 + 2][q] = a.z + u.z; Qst[d4 + 3][q] = a.w + u.w;
        }
#pragma unroll
        for (int t = 0; t < 8; t++) {
            int f = tid + t * 128;
            int k = f >> 4;
            int d4 = (f & 15) * 4;
            float4 a = *reinterpret_cast<const float4*>(&g_kp[(k0 + k) * H + h * HD + d4]);
            Ks[d4 + 0][k] = a.x; Ks[d4 + 1][k] = a.y; Ks[d4 + 2][k] = a.z; Ks[d4 + 3][k] = a.w;
        }
        __syncthreads();

        unsigned long long acc[4][4];
#pragma unroll
        for (int i = 0; i < 4; i++)
#pragma unroll
            for (int j = 0; j < 4; j++) acc[i][j] = 0ULL;

#pragma unroll
        for (int d = 0; d < HD; d++) {
            float4 a4 = *reinterpret_cast<const float4*>(&Qst[d][sg * 4]);
            ulonglong2 b0 = *reinterpret_cast<const ulonglong2*>(&Ks[d][kg * 8]);
            ulonglong2 b1 = *reinterpret_cast<const ulonglong2*>(&Ks[d][kg * 8 + 4]);
#pragma unroll
            for (int i = 0; i < 4; i++) {
                float av = (&a4.x)[i];
                unsigned long long pp = pack2(av, av);
                acc[i][0] = ffma2(pp, b0.x, acc[i][0]);
                acc[i][1] = ffma2(pp, b0.y, acc[i][1]);
                acc[i][2] = ffma2(pp, b1.x, acc[i][2]);
                acc[i][3] = ffma2(pp, b1.y, acc[i][3]);
            }
        }
#pragma unroll
        for (int i = 0; i < 4; i++) {
            int q = q0 + sg * 4 + i;
#pragma unroll
            for (int j = 0; j < 4; j++) {
                int k = k0 + kg * 8 + 2 * j;
                *reinterpret_cast<unsigned long long*>(&g_score[(h * S + q) * S + k]) = acc[i][j];
            }
        }
    } else if (b < AUX_AC_BLOCKS + AUX_TT_BLOCKS) {
        // ---------- t[h][q][e] = sum_d (qp + vb) * Wr[h*64+d][e]; 32q x 64e ----------
        float (*Qst)[36] = reinterpret_cast<float (*)[36]>(pool);           // [d][q]
        float (*Ws)[68]  = reinterpret_cast<float (*)[68]>(pool + 64 * 36); // [d][e]

        const int idx = b - AUX_AC_BLOCKS;
        const int e0 = (idx % 12) * 64;
        const int q0 = (idx / 12) * 32;

        const int qg = tid >> 4;
        const int eg = tid & 15;

        for (int h = 0; h < NH; h++) {
#pragma unroll
            for (int t = 0; t < 4; t++) {
                int f = tid + t * 128;
                int q = f >> 4;
                int d4 = (f & 15) * 4;
                float4 a = *reinterpret_cast<const float4*>(&g_qp[(q0 + q) * H + h * HD + d4]);
                float4 vb = *reinterpret_cast<const float4*>(&v_bias[h * HD + d4]);
                Qst[d4 + 0][q] = a.x + vb.x; Qst[d4 + 1][q] = a.y + vb.y;
                Qst[d4 + 2][q] = a.z + vb.z; Qst[d4 + 3][q] = a.w + vb.w;
            }
#pragma unroll
            for (int t = 0; t < 8; t++) {
                int f = tid + t * 128;
                int d = f >> 4;
                int e4 = (f & 15) * 4;
                float4 a = *reinterpret_cast<const float4*>(&Wr[(h * HD + d) * H + e0 + e4]);
                *reinterpret_cast<float4*>(&Ws[d][e4]) = a;
            }
            __syncthreads();

            unsigned long long acc[4][2];
#pragma unroll
            for (int i = 0; i < 4; i++) { acc[i][0] = 0ULL; acc[i][1] = 0ULL; }

#pragma unroll
            for (int d = 0; d < HD; d++) {
                float4 a4 = *reinterpret_cast<const float4*>(&Qst[d][qg * 4]);
                ulonglong2 bb = *reinterpret_cast<const ulonglong2*>(&Ws[d][eg * 4]);
#pragma unroll
                for (int i = 0; i < 4; i++) {
                    float av = (&a4.x)[i];
                    unsigned long long pp = pack2(av, av);
                    acc[i][0] = ffma2(pp, bb.x, acc[i][0]);
                    acc[i][1] = ffma2(pp, bb.y, acc[i][1]);
                }
            }
#pragma unroll
            for (int i = 0; i < 4; i++) {
                int q = q0 + qg * 4 + i;
#pragma unroll
                for (int j = 0; j < 2; j++) {
                    float lo, hi; unpack2(acc[i][j], lo, hi);
                    float2 r2; r2.x = lo; r2.y = hi;
                    *reinterpret_cast<float2*>(&g_tt[(h * S + q) * H + e0 + eg * 4 + 2 * j]) = r2;
                }
            }
            __syncthreads();
        }
    } else {
        // ---------- cb[h][q] = sum_d (qp + vb) * br ----------
        int idx = (b - AUX_AC_BLOCKS - AUX_TT_BLOCKS) * 128 + tid;
        if (idx < NH * S) {
            int h = idx / S, q = idx % S;
            float s = 0.f;
#pragma unroll 8
            for (int d = 0; d < HD; d++)
                s += (g_qp[q * H + h * HD + d] + v_bias[h * HD + d]) * br[h * HD + d];
            g_cb[idx] = s;
        }
    }
}

// ---------------- 3) BD + mask + softmax fused (R7/R9 proven config) ----------------
// One block per q: 256 threads (8 warps), each warp owns 64 keys (2/thread) with
// its OWN double-buffered cp.async pipeline (BD_E=32, distance 1).
#define BD_E 32                   // e-chunk width
#define BD_PAD 36                 // padded row (floats)
#define BD_NCH (H / BD_E)         // 24 chunks
#define BD_TS (H * NH)            // t2s floats: [e][h]
#define BDW_BUF (64 * BD_PAD)     // one per-warp pos buffer (2304 floats = 9216 B)
#define BD_SMEM_BYTES ((BD_TS + 8 * 2 * BDW_BUF) * 4)   // 184320 B

__device__ __forceinline__ void bd_issue_warp(const float* src_base, int ch, float* buf, int lane)
{
    unsigned int dbase = (unsigned int)__cvta_generic_to_shared(buf);
    const float* src = src_base + ch * BD_E;
#pragma unroll
    for (int t = 0; t < 16; t++) {
        int seg = lane + t * 32;          // 512 segs: 64 rows x 8 float4
        int row = seg >> 3;
        int c4  = (seg & 7) * 4;
        cp_async16(dbase + (unsigned)(row * BD_PAD + c4) * 4, src + (long)row * H + c4);
    }
}

__global__ void __launch_bounds__(256) bd_kernel(const float* __restrict__ pos,
                                                 const int* __restrict__ key_mask)
{
    extern __shared__ float sm[];
    float* t2s = sm;                        // [e*12 + h]
    __shared__ float red[8][12];
    __shared__ float bmax[12];
    __shared__ float bsum[12];

    const int tid  = threadIdx.x;
    const int wid  = tid >> 5;
    const int lane = tid & 31;
    float* wbuf0 = sm + BD_TS + wid * 2 * BDW_BUF;
    float* wbuf1 = wbuf0 + BDW_BUF;

    const int q = blockIdx.x;

    const float* psrc = pos + ((long)q * S + wid * 64) * H;

    bd_issue_warp(psrc, 0, wbuf0, lane);
    cp_commit();

#pragma unroll
    for (int t = 0; t < 9; t++) {
        int f = tid + t * 256;
        int h = f / 192;
        int r = f - h * 192;
        int e = r * 4;
        float4 v4 = *reinterpret_cast<const float4*>(&g_tt[(h * S + q) * H + e]);
        t2s[(e + 0) * 12 + h] = v4.x;
        t2s[(e + 1) * 12 + h] = v4.y;
        t2s[(e + 2) * 12 + h] = v4.z;
        t2s[(e + 3) * 12 + h] = v4.w;
    }
    __syncthreads();    // t2s visible; warps free-run from here

    unsigned long long acc0[6], acc1[6];
#pragma unroll
    for (int j = 0; j < 6; j++) { acc0[j] = 0ULL; acc1[j] = 0ULL; }

    const int ra36 = lane * BD_PAD;
    const int rb36 = (lane + 32) * BD_PAD;

    for (int ch = 0; ch < BD_NCH; ch++) {
        if (ch + 1 < BD_NCH) {
            bd_issue_warp(psrc, ch + 1, ((ch + 1) & 1) ? wbuf1 : wbuf0, lane);
            cp_commit();
            cp_wait<1>();
        } else {
            cp_wait<0>();
        }
        __syncwarp();

        const float* bp = (ch & 1) ? wbuf1 : wbuf0;
        const int e0 = ch * BD_E;
#pragma unroll
        for (int j = 0; j < 8; j++) {
            float4 pa = *reinterpret_cast<const float4*>(&bp[ra36 + 4 * j]);
            float4 pb = *reinterpret_cast<const float4*>(&bp[rb36 + 4 * j]);
            const float* tw = &t2s[(e0 + 4 * j) * 12];
#pragma unroll
            for (int i = 0; i < 4; i++) {
                float p0 = (&pa.x)[i];
                float p1 = (&pb.x)[i];
                unsigned long long pp0 = pack2(p0, p0);
                unsigned long long pp1 = pack2(p1, p1);
                const ulonglong2 w0 = *reinterpret_cast<const ulonglong2*>(&tw[i * 12 + 0]);
                const ulonglong2 w1 = *reinterpret_cast<const ulonglong2*>(&tw[i * 12 + 4]);
                const ulonglong2 w2 = *reinterpret_cast<const ulonglong2*>(&tw[i * 12 + 8]);
                acc0[0] = ffma2(pp0, w0.x, acc0[0]);
                acc0[1] = ffma2(pp0, w0.y, acc0[1]);
                acc0[2] = ffma2(pp0, w1.x, acc0[2]);
                acc0[3] = ffma2(pp0, w1.y, acc0[3]);
                acc0[4] = ffma2(pp0, w2.x, acc0[4]);
                acc0[5] = ffma2(pp0, w2.y, acc0[5]);
                acc1[0] = ffma2(pp1, w0.x, acc1[0]);
                acc1[1] = ffma2(pp1, w0.y, acc1[1]);
                acc1[2] = ffma2(pp1, w1.x, acc1[2]);
                acc1[3] = ffma2(pp1, w1.y, acc1[3]);
                acc1[4] = ffma2(pp1, w2.x, acc1[4]);
                acc1[5] = ffma2(pp1, w2.y, acc1[5]);
            }
        }
        __syncwarp();
    }

    // ---- finalize scores: s = (AC + cb + bd) * 0.125, apply mask ----
    const int kA = wid * 64 + lane;
    const int kB = kA + 32;
    const bool mA = (key_mask[kA] == 0);
    const bool mB = (key_mask[kB] == 0);

    float sA[12], sB[12];
#pragma unroll
    for (int j = 0; j < 6; j++) {
        float a0, a1, b0, b1;
        unpack2(acc0[j], a0, a1);
        unpack2(acc1[j], b0, b1);
        int h0 = 2 * j, h1 = 2 * j + 1;
        float c0 = g_cb[h0 * S + q];
        float c1 = g_cb[h1 * S + q];
        int i0 = (h0 * S + q) * S;
        int i1 = (h1 * S + q) * S;
        sA[h0] = (g_score[i0 + kA] + c0 + a0) * 0.125f;
        sA[h1] = (g_score[i1 + kA] + c1 + a1) * 0.125f;
        sB[h0] = (g_score[i0 + kB] + c0 + b0) * 0.125f;
        sB[h1] = (g_score[i1 + kB] + c1 + b1) * 0.125f;
    }
    if (mA) {
#pragma unroll
        for (int h = 0; h < 12; h++) sA[h] = -1e15f;
    }
    if (mB) {
#pragma unroll
        for (int h = 0; h < 12; h++) sB[h] = -1e15f;
    }

    // ---- block max per head ----
    float mh[12];
#pragma unroll
    for (int h = 0; h < 12; h++) mh[h] = fmaxf(sA[h], sB[h]);
#pragma unroll
    for (int o = 16; o > 0; o >>= 1) {
#pragma unroll
        for (int h = 0; h < 12; h++)
            mh[h] = fmaxf(mh[h], __shfl_xor_sync(0xffffffffu, mh[h], o));
    }
    if (lane == 0) {
#pragma unroll
        for (int h = 0; h < 12; h++) red[wid][h] = mh[h];
    }
    __syncthreads();
    if (tid < 12) {
        float m = red[0][tid];
#pragma unroll
        for (int w = 1; w < 8; w++) m = fmaxf(m, red[w][tid]);
        bmax[tid] = m;
    }
    __syncthreads();

    // ---- exp + block sum per head ----
    float eA[12], eB[12], sh[12];
#pragma unroll
    for (int h = 0; h < 12; h++) {
        float m = bmax[h];
        eA[h] = __expf(sA[h] - m);
        eB[h] = __expf(sB[h] - m);
        sh[h] = eA[h] + eB[h];
    }
#pragma unroll
    for (int o = 16; o > 0; o >>= 1) {
#pragma unroll
        for (int h = 0; h < 12; h++)
            sh[h] += __shfl_xor_sync(0xffffffffu, sh[h], o);
    }
    if (lane == 0) {
#pragma unroll
        for (int h = 0; h < 12; h++) red[wid][h] = sh[h];
    }
    __syncthreads();
    if (tid < 12) {
        float s = red[0][tid];
#pragma unroll
        for (int w = 1; w < 8; w++) s += red[w][tid];
        bsum[tid] = 1.0f / s;
    }
    __syncthreads();

    // ---- write attn ----
#pragma unroll
    for (int h = 0; h < 12; h++) {
        float inv = bsum[h];
        int base = (h * S + q) * S;
        g_score[base + kA] = eA[h] * inv;
        g_score[base + kB] = eB[h] * inv;
    }
}

// ---------------- 4) out: 16q x 64d tiles, cp.async double-buffered stages (R10 proven) ----------------
__global__ void __launch_bounds__(128) out_kernel(float* __restrict__ out)
{
    __shared__ float At[2][16][68];   // [buf][q][k]
    __shared__ float Vs[2][64][68];   // [buf][k][d]

    const int q0 = blockIdx.x * 16;
    const int h  = blockIdx.y;
    const int tid = threadIdx.x;

    const int qg = tid >> 4;       // 0..7 -> q rows qg*2, qg*2+1
    const int dg = tid & 15;       // d cols dg*4..+3

    auto issue = [&](int kc, int buf) {
        unsigned int at_base = (unsigned int)__cvta_generic_to_shared(&At[buf][0][0]);
        unsigned int vs_base = (unsigned int)__cvta_generic_to_shared(&Vs[buf][0][0]);
#pragma unroll
        for (int t = 0; t < 2; t++) {
            int f = tid + t * 128;
            int qq = f >> 4;
            int k4 = (f & 15) * 4;
            cp_async16(at_base + (unsigned)(qq * 68 + k4) * 4,
                       &g_score[(h * S + q0 + qq) * S + kc * 64 + k4]);
        }
#pragma unroll
        for (int t = 0; t < 8; t++) {
            int f = tid + t * 128;
            int k = f >> 4;
            int d4 = (f & 15) * 4;
            cp_async16(vs_base + (unsigned)(k * 68 + d4) * 4,
                       &g_vp[(kc * 64 + k) * H + h * HD + d4]);
        }
        cp_commit();
    };

    issue(0, 0);

    unsigned long long acc[2][2];
    acc[0][0] = 0ULL; acc[0][1] = 0ULL; acc[1][0] = 0ULL; acc[1][1] = 0ULL;

    for (int kc = 0; kc < 8; kc++) {
        if (kc + 1 < 8) {
            issue(kc + 1, (kc + 1) & 1);
            cp_wait<1>();
        } else {
            cp_wait<0>();
        }
        __syncthreads();

        const int buf = kc & 1;
#pragma unroll
        for (int kk = 0; kk < 64; kk++) {
            float a0 = At[buf][qg * 2 + 0][kk];
            float a1 = At[buf][qg * 2 + 1][kk];
            ulonglong2 b = *reinterpret_cast<const ulonglong2*>(&Vs[buf][kk][dg * 4]);
            unsigned long long p0 = pack2(a0, a0);
            unsigned long long p1 = pack2(a1, a1);
            acc[0][0] = ffma2(p0, b.x, acc[0][0]);
            acc[0][1] = ffma2(p0, b.y, acc[0][1]);
            acc[1][0] = ffma2(p1, b.x, acc[1][0]);
            acc[1][1] = ffma2(p1, b.y, acc[1][1]);
        }
        __syncthreads();
    }
#pragma unroll
    for (int i = 0; i < 2; i++) {
        int q = q0 + qg * 2 + i;
        float r0, r1, r2, r3;
        unpack2(acc[i][0], r0, r1);
        unpack2(acc[i][1], r2, r3);
        *reinterpret_cast<float4*>(&out[q * H + h * HD + dg * 4]) = make_float4(r0, r1, r2, r3);
    }
}

// ---------------- launch ----------------
extern "C" void kernel_launch(void* const* d_in, const int* in_sizes, int n_in,
                              void* d_out, int out_size)
{
    (void)in_sizes; (void)n_in; (void)out_size;
    const float* key      = (const float*)d_in[0];
    const float* query    = (const float*)d_in[1];
    const float* value    = (const float*)d_in[2];
    const float* pos      = (const float*)d_in[3];
    const int*   key_mask = (const int*)d_in[4];
    const float* Wk = (const float*)d_in[5];
    const float* bk = (const float*)d_in[6];
    const float* Wq = (const float*)d_in[7];
    const float* bq = (const float*)d_in[8];
    const float* Wv = (const float*)d_in[9];
    const float* bv = (const float*)d_in[10];
    const float* Wr = (const float*)d_in[11];
    const float* br = (const float*)d_in[12];
    const float* u_bias = (const float*)d_in[13];
    const float* v_bias = (const float*)d_in[14];
    float* out = (float*)d_out;

    proj_kernel<<<dim3(8, 24, 3), 128>>>(query, key, value, Wq, bq, Wk, bk, Wv, bv);
    aux_kernel<<<AUX_BLOCKS, 128>>>(Wr, br, u_bias, v_bias);

    cudaFuncSetAttribute(bd_kernel, cudaFuncAttributeMaxDynamicSharedMemorySize, BD_SMEM_BYTES);
    bd_kernel<<<S, 256, BD_SMEM_BYTES>>>(pos, key_mask);

    out_kernel<<<dim3(32, NH), 128>>>(out);
}